// round 1
// baseline (speedup 1.0000x reference)
#include <cuda_runtime.h>

// Problem constants (fixed by setup_inputs)
#define BATCH   512
#define FEAT    1024
#define THERM   3
#define IBITS   (FEAT * THERM)   // 3072
#define O1      2000
#define O2      1000
#define NLUT    64
#define NCLS    10
#define GRPSZ   (O2 / NCLS)      // 100
#define TAU     3.3333333f
#define NTHREADS 256

__global__ __launch_bounds__(NTHREADS)
void dwn_fused_kernel(const float* __restrict__ x,          // [512,1024]
                      const float* __restrict__ thr,        // [1024,3]
                      const float* __restrict__ luts1,      // [2000,64]
                      const int*   __restrict__ idx1,       // [2000,6]
                      const float* __restrict__ luts2,      // [1000,64]
                      const int*   __restrict__ idx2,       // [1000,6]
                      float*       __restrict__ out)        // [512,10]
{
    __shared__ unsigned char s_bits[IBITS];  // thermometer bits as bytes
    __shared__ float s_h1[O1];
    __shared__ float s_h2[O2];

    const int row = blockIdx.x;
    const int tid = threadIdx.x;
    const float* xr = x + row * FEAT;

    // ---- Stage 1: thermometer encode (bits are exactly 0/1) ----
    #pragma unroll
    for (int f = tid; f < FEAT; f += NTHREADS) {
        float xv = __ldg(xr + f);
        float t0 = __ldg(thr + f * 3 + 0);
        float t1 = __ldg(thr + f * 3 + 1);
        float t2 = __ldg(thr + f * 3 + 2);
        s_bits[f * 3 + 0] = (unsigned char)(xv > t0);
        s_bits[f * 3 + 1] = (unsigned char)(xv > t1);
        s_bits[f * 3 + 2] = (unsigned char)(xv > t2);
    }
    __syncthreads();

    // ---- Stage 2: LUT layer 1 — binary inputs => pure gather ----
    // index = b0*32 + b1*16 + b2*8 + b3*4 + b4*2 + b5 (MSB-first per the
    // reference's halving order).
    for (int o = tid; o < O1; o += NTHREADS) {
        const int* ip = idx1 + o * 6;
        int i0 = __ldg(ip + 0), i1 = __ldg(ip + 1), i2 = __ldg(ip + 2);
        int i3 = __ldg(ip + 3), i4 = __ldg(ip + 4), i5 = __ldg(ip + 5);
        int b0 = s_bits[i0], b1 = s_bits[i1], b2 = s_bits[i2];
        int b3 = s_bits[i3], b4 = s_bits[i4], b5 = s_bits[i5];
        int code = (b0 << 5) | (b1 << 4) | (b2 << 3) | (b3 << 2) | (b4 << 1) | b5;
        s_h1[o] = __ldg(luts1 + o * NLUT + code);
    }
    __syncthreads();

    // ---- Stage 3: LUT layer 2 — 6-D multilinear interpolation ----
    for (int o = tid; o < O2; o += NTHREADS) {
        const int* ip = idx2 + o * 6;
        float xk[6];
        #pragma unroll
        for (int k = 0; k < 6; k++) {
            xk[k] = s_h1[__ldg(ip + k)];
        }

        // Load 64 LUT entries (16 x LDG.128, luts2 rows are 256B-aligned)
        float v[NLUT];
        const float4* lp = reinterpret_cast<const float4*>(luts2 + o * NLUT);
        #pragma unroll
        for (int j = 0; j < NLUT / 4; j++) {
            float4 t = __ldg(lp + j);
            v[4 * j + 0] = t.x;
            v[4 * j + 1] = t.y;
            v[4 * j + 2] = t.z;
            v[4 * j + 3] = t.w;
        }

        // Halving reduction: step k contracts with xk[k] against stride 32>>k
        #pragma unroll
        for (int k = 0; k < 6; k++) {
            const int half = 32 >> k;
            #pragma unroll
            for (int j = 0; j < 32; j++) {  // j < half guarded below (const-folds)
                if (j < half) {
                    v[j] = v[j] + (v[j + half] - v[j]) * xk[k];
                }
            }
        }
        s_h2[o] = v[0];
    }
    __syncthreads();

    // ---- Stage 4: grouped class sum (deterministic fixed-order reduction) ----
    if (tid < NCLS) {
        const float* hp = s_h2 + tid * GRPSZ;
        float s0 = 0.f, s1 = 0.f, s2 = 0.f, s3 = 0.f;
        #pragma unroll
        for (int j = 0; j < GRPSZ; j += 4) {
            s0 += hp[j + 0];
            s1 += hp[j + 1];
            s2 += hp[j + 2];
            s3 += hp[j + 3];
        }
        out[row * NCLS + tid] = ((s0 + s1) + (s2 + s3)) / TAU;
    }
}

extern "C" void kernel_launch(void* const* d_in, const int* in_sizes, int n_in,
                              void* d_out, int out_size)
{
    const float* x      = (const float*)d_in[0];
    const float* thr    = (const float*)d_in[1];
    const float* luts1  = (const float*)d_in[2];
    const int*   idx1   = (const int*)  d_in[3];
    const float* luts2  = (const float*)d_in[4];
    const int*   idx2   = (const int*)  d_in[5];
    float*       out    = (float*)d_out;

    dwn_fused_kernel<<<BATCH, NTHREADS>>>(x, thr, luts1, idx1, luts2, idx2, out);
}

// round 2
// speedup vs baseline: 1.0349x; 1.0349x over previous
#include <cuda_runtime.h>

// ---------------- Problem constants (fixed by setup_inputs) ----------------
#define BATCH    512
#define FEAT     1024
#define THERM    3
#define IBITS    (FEAT * THERM)     // 3072 bits = 96 words per row
#define WORDS    96
#define O1       2000
#define O2       1000
#define NLUT     64
#define NCLS     10
#define TAU      3.3333333f

#define RG       8                  // rows per row-group
#define NGRP     (BATCH / RG)       // 64 row-groups

// Kernel A (layer 1) split
#define A_OSPL   8
#define A_OUT    (O1 / A_OSPL)      // 250 outputs per CTA

// Kernel B (layer 2) split: 5 splits x 200 outputs = 2 classes per CTA
#define B_OSPL   5
#define B_OUT    (O2 / B_OSPL)      // 200
#define H1S      9                  // padded row stride for h1 (bank spread)
#define L2S      68                 // padded float stride for luts2 rows in smem

// ---------------- Device scratch (no allocations allowed) ----------------
__device__ unsigned g_bits[BATCH * WORDS];               // 192 KB packed thermometer bits
__device__ float    g_h1[NGRP * O1 * H1S];               // 64*2000*9 floats ~ 4.6 MB

// ---------------- f32x2 packed-math helpers (sm_10x) ----------------
__device__ __forceinline__ unsigned long long pk2(float lo, float hi) {
    unsigned long long r;
    asm("mov.b64 %0, {%1, %2};" : "=l"(r) : "f"(lo), "f"(hi));
    return r;
}
__device__ __forceinline__ void upk2(float& lo, float& hi, unsigned long long v) {
    asm("mov.b64 {%0, %1}, %2;" : "=f"(lo), "=f"(hi) : "l"(v));
}
__device__ __forceinline__ unsigned long long fma2(unsigned long long a,
                                                   unsigned long long b,
                                                   unsigned long long c) {
    unsigned long long d;
    asm("fma.rn.f32x2 %0, %1, %2, %3;" : "=l"(d) : "l"(a), "l"(b), "l"(c));
    return d;
}
// lerp over both lanes: a + x*(b-a) computed as fma(x, b, fma(-x, a, a))
__device__ __forceinline__ unsigned long long lerp2(unsigned long long a,
                                                    unsigned long long b,
                                                    unsigned long long x,
                                                    unsigned long long nx) {
    return fma2(x, b, fma2(nx, a, a));
}

// ================== Kernel 0: thermometer encode -> packed bits ==================
// grid 128, block 384. CTA handles 4 rows; thread owns one 32-bit word.
__global__ __launch_bounds__(384)
void k0_thermo(const float* __restrict__ x, const float* __restrict__ thr)
{
    int r = blockIdx.x * 4 + threadIdx.x / WORDS;
    int w = threadIdx.x % WORDS;
    int base = w * 32;                      // first bit index of this word
    int f_lo = base / THERM;
    int f_hi = (base + 31) / THERM;
    unsigned word = 0;
    for (int f = f_lo; f <= f_hi; f++) {
        float xv = __ldg(x + r * FEAT + f);
        #pragma unroll
        for (int t = 0; t < THERM; t++) {
            int pos = f * THERM + t - base;
            if (pos >= 0 && pos < 32) {
                word |= (unsigned)(xv > __ldg(thr + f * THERM + t)) << pos;
            }
        }
    }
    g_bits[r * WORDS + w] = word;
}

// ================== Kernel A: layer 1 (binary inputs => gather) ==================
// grid 64*8 = 512 CTAs, 256 threads. Lane layout: task t -> (o = t>>3, r = t&7)
// so the 8 lanes of one output share a luts1 row (coalescer merges the gather).
__global__ __launch_bounds__(256)
void kA_layer1(const float* __restrict__ luts1, const int* __restrict__ idx1)
{
    __shared__ unsigned s_bits[RG * (WORDS + 1)];   // stride 97 kills bank conflicts
    __shared__ int      s_idx[A_OUT * 6];

    const int g     = blockIdx.x >> 3;
    const int os    = blockIdx.x & 7;
    const int obase = os * A_OUT;
    const int tid   = threadIdx.x;

    for (int i = tid; i < RG * WORDS; i += 256) {
        int r = i / WORDS, w = i % WORDS;
        s_bits[r * (WORDS + 1) + w] = g_bits[(g * RG + r) * WORDS + w];
    }
    for (int i = tid; i < A_OUT * 6; i += 256)
        s_idx[i] = __ldg(idx1 + obase * 6 + i);
    __syncthreads();

    for (int t = tid; t < A_OUT * RG; t += 256) {
        int ol = t >> 3;
        int r  = t & 7;
        int code = 0;
        #pragma unroll
        for (int k = 0; k < 6; k++) {
            int i = s_idx[ol * 6 + k];
            unsigned wv = s_bits[r * (WORDS + 1) + (i >> 5)];
            code = (code << 1) | (int)((wv >> (i & 31)) & 1u);
        }
        float v = __ldg(luts1 + (obase + ol) * NLUT + code);
        g_h1[(g * O1 + obase + ol) * H1S + r] = v;
    }
}

// ================== Kernel B: layer 2 interp + class sums ==================
// grid 64*5 = 320 CTAs, 256 threads, ~134 KB dynamic smem (1 CTA/SM).
// Thread (p, rh): packs outputs (p, p+100) into f32x2 lanes, handles 4 rows.
__global__ __launch_bounds__(256, 1)
void kB_layer2(const float* __restrict__ luts2, const int* __restrict__ idx2,
               float* __restrict__ out)
{
    extern __shared__ char smem[];
    float* s_h1  = (float*)smem;                               // O1*H1S  = 18000 f
    float* s_l2  = s_h1 + O1 * H1S;                            // B_OUT*L2S = 13600 f
    int*   s_idx = (int*)(s_l2 + B_OUT * L2S);                 // B_OUT*6 = 1200 i
    float* s_h2  = (float*)(s_idx + B_OUT * 6);                // B_OUT*RG = 1600 f

    const int g     = blockIdx.x / B_OSPL;
    const int os    = blockIdx.x % B_OSPL;
    const int obase = os * B_OUT;
    const int tid   = threadIdx.x;

    // ---- stage h1 (straight 72 KB copy, float2) ----
    {
        const float2* src = (const float2*)(g_h1 + g * O1 * H1S);
        float2* dst = (float2*)s_h1;
        for (int i = tid; i < O1 * H1S / 2; i += 256) dst[i] = src[i];
    }
    // ---- stage luts2 slice (coalesced read, padded store) ----
    {
        const float4* src = (const float4*)(luts2 + obase * NLUT);
        for (int i = tid; i < B_OUT * (NLUT / 4); i += 256) {
            int o = i >> 4, j4 = i & 15;
            float4 v = __ldg(src + i);
            *(float4*)(s_l2 + o * L2S + j4 * 4) = v;
        }
    }
    // ---- stage idx2 slice ----
    for (int i = tid; i < B_OUT * 6; i += 256)
        s_idx[i] = __ldg(idx2 + obase * 6 + i);
    __syncthreads();

    if (tid < B_OUT) {
        const int p  = tid >> 1;       // pair id: outputs (p, p+100)
        const int rh = tid & 1;        // row half: rows [rh*4, rh*4+4)
        const int oA = p;
        const int oB = p + 100;

        // pack the two LUT rows into f32x2 registers (shared across 4 rows)
        unsigned long long v2[NLUT];
        {
            const float* LA = s_l2 + oA * L2S;
            const float* LB = s_l2 + oB * L2S;
            #pragma unroll
            for (int j = 0; j < NLUT; j += 4) {
                float4 a = *(const float4*)(LA + j);
                float4 b = *(const float4*)(LB + j);
                v2[j + 0] = pk2(a.x, b.x);
                v2[j + 1] = pk2(a.y, b.y);
                v2[j + 2] = pk2(a.z, b.z);
                v2[j + 3] = pk2(a.w, b.w);
            }
        }
        int ia[6], ib[6];
        #pragma unroll
        for (int k = 0; k < 6; k++) {
            ia[k] = s_idx[oA * 6 + k];
            ib[k] = s_idx[oB * 6 + k];
        }

        #pragma unroll
        for (int rr = 0; rr < 4; rr++) {
            const int r = rh * 4 + rr;
            unsigned long long xp[6], xn[6];
            #pragma unroll
            for (int k = 0; k < 6; k++) {
                float xa = s_h1[ia[k] * H1S + r];
                float xb = s_h1[ib[k] * H1S + r];
                xp[k] = pk2(xa, xb);
                xn[k] = pk2(-xa, -xb);
            }
            // levels 0+1 fused: 64 -> 16
            unsigned long long u[16];
            #pragma unroll
            for (int j = 0; j < 16; j++) {
                unsigned long long wab = lerp2(v2[j],      v2[j + 32], xp[0], xn[0]);
                unsigned long long wcd = lerp2(v2[j + 16], v2[j + 48], xp[0], xn[0]);
                u[j] = lerp2(wab, wcd, xp[1], xn[1]);
            }
            // levels 2..5: 16 -> 1
            #pragma unroll
            for (int k = 2; k < 6; k++) {
                const int half = 16 >> (k - 1);
                #pragma unroll
                for (int j = 0; j < 16; j++) {
                    if (j < half) u[j] = lerp2(u[j], u[j + half], xp[k], xn[k]);
                }
            }
            float hA, hB;
            upk2(hA, hB, u[0]);
            s_h2[oA * RG + r] = hA;
            s_h2[oB * RG + r] = hB;
        }
    }
    __syncthreads();

    // ---- deterministic fixed-order class sums: 2 classes x 8 rows ----
    if (tid < 2 * RG) {
        const int c = tid >> 3;        // local class 0/1
        const int r = tid & 7;
        const float* hp = s_h2 + c * 100 * RG + r;
        float s0 = 0.f, s1 = 0.f;
        #pragma unroll 4
        for (int j = 0; j < 100; j += 2) {
            s0 += hp[(j + 0) * RG];
            s1 += hp[(j + 1) * RG];
        }
        const int row = g * RG + r;
        const int cls = os * 2 + c;
        out[row * NCLS + cls] = (s0 + s1) / TAU;
    }
}

// ================== launch ==================
extern "C" void kernel_launch(void* const* d_in, const int* in_sizes, int n_in,
                              void* d_out, int out_size)
{
    const float* x      = (const float*)d_in[0];
    const float* thr    = (const float*)d_in[1];
    const float* luts1  = (const float*)d_in[2];
    const int*   idx1   = (const int*)  d_in[3];
    const float* luts2  = (const float*)d_in[4];
    const int*   idx2   = (const int*)  d_in[5];
    float*       out    = (float*)d_out;

    const int smemB = (O1 * H1S + B_OUT * L2S + B_OUT * RG) * 4 + B_OUT * 6 * 4;
    static bool attr_set = false;
    if (!attr_set) {
        cudaFuncSetAttribute(kB_layer2, cudaFuncAttributeMaxDynamicSharedMemorySize, smemB);
        attr_set = true;
    }

    k0_thermo<<<BATCH / 4, 384>>>(x, thr);
    kA_layer1<<<NGRP * A_OSPL, 256>>>(luts1, idx1);
    kB_layer2<<<NGRP * B_OSPL, 256, smemB>>>(luts2, idx2, out);
}

// round 3
// speedup vs baseline: 1.0946x; 1.0576x over previous
#include <cuda_runtime.h>

// ---------------- Problem constants (fixed by setup_inputs) ----------------
#define BATCH    512
#define FEAT     1024
#define THERM    3
#define WORDS    96                 // 3072 bits per row
#define O1       2000
#define O2       1000
#define NLUT     64
#define NCLS     10
#define TAU      3.3333333f

#define RG       8                  // rows per row-group
#define NGRP     (BATCH / RG)       // 64

#define A_OSPL   8
#define A_OUT    (O1 / A_OSPL)      // 250

#define B_OSPL   5
#define B_OUT    (O2 / B_OSPL)      // 200 outputs = 100 f32x2 pairs
#define NPAIR    (B_OUT / 2)        // 100
#define H1S      9                  // padded smem stride for h1 rows

// ---------------- Device scratch (no allocations allowed) ----------------
__device__ unsigned g_bits[BATCH * WORDS];        // 192 KB
__device__ float    g_h1[NGRP * O1 * RG];         // 4 MB, layout [g][o][r]

// ---------------- f32x2 packed-math helpers (sm_10x) ----------------
__device__ __forceinline__ unsigned long long pk2(float lo, float hi) {
    unsigned long long r;
    asm("mov.b64 %0, {%1, %2};" : "=l"(r) : "f"(lo), "f"(hi));
    return r;
}
__device__ __forceinline__ void upk2(float& lo, float& hi, unsigned long long v) {
    asm("mov.b64 {%0, %1}, %2;" : "=f"(lo), "=f"(hi) : "l"(v));
}
__device__ __forceinline__ unsigned long long fma2(unsigned long long a,
                                                   unsigned long long b,
                                                   unsigned long long c) {
    unsigned long long d;
    asm("fma.rn.f32x2 %0, %1, %2, %3;" : "=l"(d) : "l"(a), "l"(b), "l"(c));
    return d;
}
// a + x*(b-a) on both lanes: fma(x, b, fma(-x, a, a))
__device__ __forceinline__ unsigned long long lerp2(unsigned long long a,
                                                    unsigned long long b,
                                                    unsigned long long x,
                                                    unsigned long long nx) {
    return fma2(x, b, fma2(nx, a, a));
}

// ================== Kernel 0: thermometer encode via warp ballots ==================
// One lane per (row, feature). Warp covers 32 consecutive features of one row.
// Bit layout: word index = t*32 + (f>>5), bit position = f&31.
__global__ __launch_bounds__(256)
void k0_thermo(const float* __restrict__ x, const float* __restrict__ thr)
{
    const int W    = blockIdx.x * 8 + (threadIdx.x >> 5);   // global warp id
    const int lane = threadIdx.x & 31;
    const int row  = W >> 5;          // 512 rows
    const int chnk = W & 31;          // 32 feature-chunks
    const int f    = chnk * 32 + lane;

    float xv = __ldg(x + row * FEAT + f);
    float t0 = __ldg(thr + f * 3 + 0);
    float t1 = __ldg(thr + f * 3 + 1);
    float t2 = __ldg(thr + f * 3 + 2);

    unsigned b0 = __ballot_sync(0xFFFFFFFFu, xv > t0);
    unsigned b1 = __ballot_sync(0xFFFFFFFFu, xv > t1);
    unsigned b2 = __ballot_sync(0xFFFFFFFFu, xv > t2);

    if (lane == 0) {
        unsigned* wp = g_bits + row * WORDS + chnk;
        wp[0]  = b0;
        wp[32] = b1;
        wp[64] = b2;
    }
}

// ================== Kernel A: layer 1 (binary inputs => pure gather) ==================
// grid 64*8 = 512 CTAs, 256 threads. Task t -> (o = t>>3, r = t&7): the 8 lanes
// of one output share a luts1 row. g_h1 written contiguously (128B per warp).
__global__ __launch_bounds__(256)
void kA_layer1(const float* __restrict__ luts1, const int* __restrict__ idx1)
{
    __shared__ unsigned s_bits[RG * (WORDS + 1)];   // stride 97
    __shared__ int      s_idx[A_OUT * 6];

    const int g     = blockIdx.x >> 3;
    const int os    = blockIdx.x & 7;
    const int obase = os * A_OUT;
    const int tid   = threadIdx.x;

    for (int i = tid; i < RG * WORDS; i += 256) {
        int r = i / WORDS, w = i % WORDS;
        s_bits[r * (WORDS + 1) + w] = g_bits[(g * RG + r) * WORDS + w];
    }
    for (int i = tid; i < A_OUT * 6; i += 256)
        s_idx[i] = __ldg(idx1 + obase * 6 + i);
    __syncthreads();

    for (int t = tid; t < A_OUT * RG; t += 256) {
        const int ol = t >> 3;
        const int r  = t & 7;
        const unsigned* bp = s_bits + r * (WORDS + 1);
        int code = 0;
        #pragma unroll
        for (int k = 0; k < 6; k++) {
            unsigned i  = (unsigned)s_idx[ol * 6 + k];
            unsigned f  = i / 3u;              // magic-multiply div
            unsigned tt = i - f * 3u;
            unsigned wv = bp[tt * 32 + (f >> 5)];
            code = (code << 1) | (int)((wv >> (f & 31)) & 1u);
        }
        float v = __ldg(luts1 + (obase + ol) * NLUT + code);
        g_h1[(g * O1 + obase + ol) * RG + r] = v;   // coalesced
    }
}

// ================== Kernel B: layer 2 interp + class sums ==================
// grid 64*5 = 320 CTAs, 256 threads, ~134 KB dyn smem (1 CTA/SM).
// LUT rows of pair (p, p+100) interleaved as float2 in [j][p] layout;
// levels 0+1 consumed from smem (conflict-free LDS.64), levels 2..5 in regs.
__global__ __launch_bounds__(256, 1)
void kB_layer2(const float* __restrict__ luts2, const int* __restrict__ idx2,
               float* __restrict__ out)
{
    extern __shared__ char smem[];
    float*              s_h1  = (float*)smem;                      // O1*H1S = 18000 f (72 KB)
    unsigned long long* s_l2p = (unsigned long long*)(s_h1 + O1 * H1S); // 64*100 u64 (51.2 KB)
    int*                s_idx = (int*)(s_l2p + NLUT * NPAIR);      // 1200 i (4.8 KB)
    float*              s_h2  = (float*)(s_idx + B_OUT * 6);       // 1600 f (6.4 KB)

    const int g     = blockIdx.x / B_OSPL;
    const int os    = blockIdx.x % B_OSPL;
    const int obase = os * B_OUT;
    const int tid   = threadIdx.x;

    // ---- stage h1: global [o][r] contiguous -> smem stride-9 ----
    {
        const float4* src = (const float4*)(g_h1 + g * O1 * RG);
        for (int i = tid; i < O1 * RG / 4; i += 256) {
            float4 v = __ldg(src + i);
            int o = i >> 1, sub = (i & 1) * 4;
            float* d = s_h1 + o * H1S + sub;
            d[0] = v.x; d[1] = v.y; d[2] = v.z; d[3] = v.w;
        }
    }
    // ---- stage luts2 slice: interleave pair rows into [j][p] float2 ----
    {
        float* l2f = (float*)s_l2p;
        for (int i = tid; i < B_OUT * (NLUT / 4); i += 256) {
            int o = i >> 4, q = i & 15;
            float4 v = __ldg((const float4*)(luts2 + (obase + o) * NLUT) + q);
            int p  = (o >= NPAIR) ? (o - NPAIR) : o;
            int hi = (o >= NPAIR) ? 1 : 0;
            int j0 = q * 4;
            l2f[((j0 + 0) * NPAIR + p) * 2 + hi] = v.x;
            l2f[((j0 + 1) * NPAIR + p) * 2 + hi] = v.y;
            l2f[((j0 + 2) * NPAIR + p) * 2 + hi] = v.z;
            l2f[((j0 + 3) * NPAIR + p) * 2 + hi] = v.w;
        }
    }
    for (int i = tid; i < B_OUT * 6; i += 256)
        s_idx[i] = __ldg(idx2 + obase * 6 + i);
    __syncthreads();

    if (tid < 2 * NPAIR) {
        const int p  = tid >> 1;
        const int rh = tid & 1;

        int ia[6], ib[6];
        #pragma unroll
        for (int k = 0; k < 6; k++) {
            ia[k] = s_idx[p * 6 + k] * H1S;
            ib[k] = s_idx[(p + NPAIR) * 6 + k] * H1S;
        }
        const unsigned long long* Lp = s_l2p + p;

        #pragma unroll
        for (int rr = 0; rr < 4; rr++) {
            const int r = rh * 4 + rr;
            unsigned long long xp[6], xn[6];
            #pragma unroll
            for (int k = 0; k < 6; k++) {
                float xa = s_h1[ia[k] + r];
                float xb = s_h1[ib[k] + r];
                xp[k] = pk2(xa, xb);
                xn[k] = pk2(-xa, -xb);
            }
            // levels 0+1 straight from smem: 64 -> 16
            unsigned long long u[16];
            #pragma unroll
            for (int j = 0; j < 16; j++) {
                unsigned long long a = Lp[(j +  0) * NPAIR];
                unsigned long long c = Lp[(j + 32) * NPAIR];
                unsigned long long b = Lp[(j + 16) * NPAIR];
                unsigned long long d = Lp[(j + 48) * NPAIR];
                u[j] = lerp2(lerp2(a, c, xp[0], xn[0]),
                             lerp2(b, d, xp[0], xn[0]), xp[1], xn[1]);
            }
            // levels 2..5 in registers: 16 -> 1
            #pragma unroll
            for (int k = 2; k < 6; k++) {
                const int half = 16 >> (k - 1);
                #pragma unroll
                for (int j = 0; j < 16; j++) {
                    if (j < half) u[j] = lerp2(u[j], u[j + half], xp[k], xn[k]);
                }
            }
            float hA, hB;
            upk2(hA, hB, u[0]);
            s_h2[p * RG + r]           = hA;
            s_h2[(p + NPAIR) * RG + r] = hB;
        }
    }
    __syncthreads();

    // ---- deterministic fixed-order class sums: 2 classes x 8 rows ----
    if (tid < 2 * RG) {
        const int c = tid >> 3;
        const int r = tid & 7;
        const float* hp = s_h2 + c * NPAIR * RG + r;
        float s0 = 0.f, s1 = 0.f;
        #pragma unroll 4
        for (int j = 0; j < NPAIR; j += 2) {
            s0 += hp[(j + 0) * RG];
            s1 += hp[(j + 1) * RG];
        }
        out[(g * RG + r) * NCLS + os * 2 + c] = (s0 + s1) / TAU;
    }
}

// ================== launch ==================
extern "C" void kernel_launch(void* const* d_in, const int* in_sizes, int n_in,
                              void* d_out, int out_size)
{
    const float* x      = (const float*)d_in[0];
    const float* thr    = (const float*)d_in[1];
    const float* luts1  = (const float*)d_in[2];
    const int*   idx1   = (const int*)  d_in[3];
    const float* luts2  = (const float*)d_in[4];
    const int*   idx2   = (const int*)  d_in[5];
    float*       out    = (float*)d_out;

    const int smemB = (O1 * H1S) * 4 + NLUT * NPAIR * 8 + B_OUT * 6 * 4 + B_OUT * RG * 4;
    static bool attr_set = false;
    if (!attr_set) {
        cudaFuncSetAttribute(kB_layer2, cudaFuncAttributeMaxDynamicSharedMemorySize, smemB);
        attr_set = true;
    }

    k0_thermo<<<BATCH * FEAT / 256, 256>>>(x, thr);
    kA_layer1<<<NGRP * A_OSPL, 256>>>(luts1, idx1);
    kB_layer2<<<NGRP * B_OSPL, 256, smemB>>>(luts2, idx2, out);
}

// round 4
// speedup vs baseline: 1.3378x; 1.2222x over previous
#include <cuda_runtime.h>

// ---------------- Problem constants ----------------
#define BATCH    512
#define FEAT     1024
#define O1       2000
#define O2       1000
#define NLUT     64
#define NCLS     10
#define TAU      3.3333333f

#define RG       8                  // rows per row-group
#define NGRP     (BATCH / RG)       // 64

#define A_OSPL   4
#define A_OUT    (O1 / A_OSPL)      // 500

#define B_OSPL   5
#define B_OUT    (O2 / B_OSPL)      // 200 outputs = 100 output-pairs
#define NPAIR    (B_OUT / 2)        // 100
#define H1S      9                  // padded smem stride for h1 rows
#define L2PS     66                 // padded u64 stride per LUT pair (528B)

// ---------------- Device scratch ----------------
__device__ float g_h1[NGRP * O1 * RG];      // 4 MB, layout [g][o][r]

// ---------------- f32x2 helpers (sm_10x packed fp32) ----------------
__device__ __forceinline__ unsigned long long pk2(float lo, float hi) {
    unsigned long long r;
    asm("mov.b64 %0, {%1, %2};" : "=l"(r) : "f"(lo), "f"(hi));
    return r;
}
__device__ __forceinline__ void upk2(float& lo, float& hi, unsigned long long v) {
    asm("mov.b64 {%0, %1}, %2;" : "=f"(lo), "=f"(hi) : "l"(v));
}
__device__ __forceinline__ unsigned long long fma2(unsigned long long a,
                                                   unsigned long long b,
                                                   unsigned long long c) {
    unsigned long long d;
    asm("fma.rn.f32x2 %0, %1, %2, %3;" : "=l"(d) : "l"(a), "l"(b), "l"(c));
    return d;
}
// a + x*(b-a) on both lanes
__device__ __forceinline__ unsigned long long lerp2(unsigned long long a,
                                                    unsigned long long b,
                                                    unsigned long long x,
                                                    unsigned long long nx) {
    return fma2(x, b, fma2(nx, a, a));
}

// ============ Kernel 1: thermometer (in-CTA) + layer 1 gather ============
// grid 64*4 = 256 CTAs, 256 threads. CTA (g, os): rows g*8..g*8+7, outputs
// os*500..+500. Bits live only in smem (word = t*32 + (f>>5), bit = f&31).
__global__ __launch_bounds__(256)
void k01_layer1(const float* __restrict__ x,   const float* __restrict__ thr,
                const float* __restrict__ luts1, const int* __restrict__ idx1)
{
    __shared__ unsigned s_bits[RG * 97];      // stride 97 (96 words + pad)
    __shared__ int      s_idx[A_OUT * 6];

    const int g     = blockIdx.x >> 2;
    const int os    = blockIdx.x & 3;
    const int obase = os * A_OUT;
    const int tid   = threadIdx.x;
    const int lane  = tid & 31;

    // ---- thermometer: 8 rows x 1024 features, warp covers 32 consecutive f ----
    for (int i = tid; i < RG * FEAT; i += 256) {
        const int r = i >> 10;
        const int f = i & 1023;
        float xv = __ldg(x + (g * RG + r) * FEAT + f);
        unsigned b0 = __ballot_sync(0xFFFFFFFFu, xv > __ldg(thr + f * 3 + 0));
        unsigned b1 = __ballot_sync(0xFFFFFFFFu, xv > __ldg(thr + f * 3 + 1));
        unsigned b2 = __ballot_sync(0xFFFFFFFFu, xv > __ldg(thr + f * 3 + 2));
        if (lane == 0) {
            unsigned* wp = s_bits + r * 97 + (f >> 5);
            wp[0]  = b0;
            wp[32] = b1;
            wp[64] = b2;
        }
    }
    for (int i = tid; i < A_OUT * 6; i += 256)
        s_idx[i] = __ldg(idx1 + obase * 6 + i);
    __syncthreads();

    // ---- layer 1: pure gather, task t -> (o = t>>3, r = t&7) ----
    for (int t = tid; t < A_OUT * RG; t += 256) {
        const int ol = t >> 3;
        const int r  = t & 7;
        const unsigned* bp = s_bits + r * 97;
        int code = 0;
        #pragma unroll
        for (int k = 0; k < 6; k++) {
            unsigned i  = (unsigned)s_idx[ol * 6 + k];
            unsigned f  = i / 3u;
            unsigned tt = i - f * 3u;
            unsigned wv = bp[tt * 32 + (f >> 5)];
            code = (code << 1) | (int)((wv >> (f & 31)) & 1u);
        }
        g_h1[(g * O1 + obase + ol) * RG + r] =
            __ldg(luts1 + (obase + ol) * NLUT + code);   // coalesced store
    }
}

// ============ Kernel 2: layer 2 interp + class sums ============
// grid 64*5 = 320 CTAs, 512 threads, ~133 KB dyn smem (1 CTA/SM).
// Pair LUT stored as u64 [p][j] with stride 66 (conflict-free LDS.128).
// Reduction contracts LSB-first so every level is an adjacent-pair lerp.
__global__ __launch_bounds__(512, 1)
void kB_layer2(const float* __restrict__ luts2, const int* __restrict__ idx2,
               float* __restrict__ out)
{
    extern __shared__ char smem[];
    float*              s_h1  = (float*)smem;                        // 18000 f
    unsigned long long* s_l2p = (unsigned long long*)(s_h1 + O1 * H1S); // 100*66 u64
    int*                s_idx = (int*)(s_l2p + NPAIR * L2PS);        // 1200 i
    float*              s_h2  = (float*)(s_idx + B_OUT * 6);         // 1600 f

    const int g     = blockIdx.x / B_OSPL;
    const int os    = blockIdx.x % B_OSPL;
    const int obase = os * B_OUT;
    const int tid   = threadIdx.x;

    // ---- stage h1: global [o][r] -> smem stride-9 ----
    {
        const float4* src = (const float4*)(g_h1 + g * O1 * RG);
        for (int i = tid; i < O1 * RG / 4; i += 512) {
            float4 v = __ldg(src + i);
            float* d = s_h1 + (i >> 1) * H1S + (i & 1) * 4;
            d[0] = v.x; d[1] = v.y; d[2] = v.z; d[3] = v.w;
        }
    }
    // ---- stage luts2 pair-interleaved: s_l2p[p*66 + j] = (rowA[j], rowB[j]) ----
    for (int i = tid; i < NPAIR * (NLUT / 4); i += 512) {
        const int p = i >> 4, q = i & 15;
        float4 a = __ldg((const float4*)(luts2 + (obase + p) * NLUT) + q);
        float4 b = __ldg((const float4*)(luts2 + (obase + NPAIR + p) * NLUT) + q);
        unsigned long long* d = s_l2p + p * L2PS + q * 4;
        d[0] = pk2(a.x, b.x);
        d[1] = pk2(a.y, b.y);
        d[2] = pk2(a.z, b.z);
        d[3] = pk2(a.w, b.w);
    }
    for (int i = tid; i < B_OUT * 6; i += 512)
        s_idx[i] = __ldg(idx2 + obase * 6 + i);
    __syncthreads();

    if (tid < 4 * NPAIR) {
        const int p  = tid >> 2;       // pair id (4 lanes share -> LDS broadcast)
        const int rh = tid & 3;        // row pair: rows rh*2, rh*2+1

        int ia[6], ib[6];
        #pragma unroll
        for (int k = 0; k < 6; k++) {
            ia[k] = s_idx[p * 6 + k] * H1S;
            ib[k] = s_idx[(p + NPAIR) * 6 + k] * H1S;
        }
        const unsigned long long* Lp = s_l2p + p * L2PS;

        #pragma unroll
        for (int rr = 0; rr < 2; rr++) {
            const int r = rh * 2 + rr;
            unsigned long long xp[6], xn[6];
            #pragma unroll
            for (int k = 0; k < 6; k++) {
                float xa = s_h1[ia[k] + r];
                float xb = s_h1[ib[k] + r];
                xp[k] = pk2(xa, xb);
                xn[k] = pk2(-xa, -xb);
            }
            // levels x5, x4 straight from smem: 64 -> 16 (LDS.128 pairs)
            unsigned long long u[16];
            #pragma unroll
            for (int t = 0; t < 16; t++) {
                ulonglong2 c01 = *(const ulonglong2*)(Lp + 4 * t);
                ulonglong2 c23 = *(const ulonglong2*)(Lp + 4 * t + 2);
                unsigned long long w0 = lerp2(c01.x, c01.y, xp[5], xn[5]);
                unsigned long long w1 = lerp2(c23.x, c23.y, xp[5], xn[5]);
                u[t] = lerp2(w0, w1, xp[4], xn[4]);
            }
            // levels x3..x0 in registers: adjacent pairs, 16 -> 1
            #pragma unroll
            for (int k = 3; k >= 0; k--) {
                const int m = 1 << k;
                #pragma unroll
                for (int j = 0; j < 8; j++) {
                    if (j < m) u[j] = lerp2(u[2 * j], u[2 * j + 1], xp[k], xn[k]);
                }
            }
            float hA, hB;
            upk2(hA, hB, u[0]);
            s_h2[p * RG + r]           = hA;
            s_h2[(p + NPAIR) * RG + r] = hB;
        }
    }
    __syncthreads();

    // ---- deterministic fixed-order class sums: 2 classes x 8 rows ----
    if (tid < 2 * RG) {
        const int c = tid >> 3;
        const int r = tid & 7;
        const float* hp = s_h2 + c * NPAIR * RG + r;
        float s0 = 0.f, s1 = 0.f;
        #pragma unroll 4
        for (int j = 0; j < NPAIR; j += 2) {
            s0 += hp[(j + 0) * RG];
            s1 += hp[(j + 1) * RG];
        }
        out[(g * RG + r) * NCLS + os * 2 + c] = (s0 + s1) / TAU;
    }
}

// ================== launch ==================
extern "C" void kernel_launch(void* const* d_in, const int* in_sizes, int n_in,
                              void* d_out, int out_size)
{
    const float* x      = (const float*)d_in[0];
    const float* thr    = (const float*)d_in[1];
    const float* luts1  = (const float*)d_in[2];
    const int*   idx1   = (const int*)  d_in[3];
    const float* luts2  = (const float*)d_in[4];
    const int*   idx2   = (const int*)  d_in[5];
    float*       out    = (float*)d_out;

    const int smemB = (O1 * H1S) * 4 + NPAIR * L2PS * 8 + B_OUT * 6 * 4 + B_OUT * RG * 4;
    static bool attr_set = false;
    if (!attr_set) {
        cudaFuncSetAttribute(kB_layer2, cudaFuncAttributeMaxDynamicSharedMemorySize, smemB);
        attr_set = true;
    }

    k01_layer1<<<NGRP * A_OSPL, 256>>>(x, thr, luts1, idx1);
    kB_layer2<<<NGRP * B_OSPL, 512, smemB>>>(luts2, idx2, out);
}

// round 5
// speedup vs baseline: 1.5174x; 1.1342x over previous
#include <cuda_runtime.h>

// ---------------- Problem constants ----------------
#define BATCH    512
#define FEAT     1024
#define O1       2000
#define O2       1000
#define NLUT     64
#define NCLS     10
#define TAU      3.3333333f

// kA row grouping: 8 rows per CTA (thermometer amortization)
#define RGA      8
#define NGA      (BATCH / RGA)      // 64
#define A_OSPL   2
#define A_OUT    (O1 / A_OSPL)      // 1000

// kB row grouping: 4 rows per CTA (small smem -> 2 CTAs/SM)
#define RG       4
#define NG4      (BATCH / RG)       // 128
#define B_OSPL   5
#define B_OUT    (O2 / B_OSPL)      // 200 outputs = exactly 2 classes
#define NPAIR    (B_OUT / 2)        // 100
#define H1S      5                  // padded smem stride for h1 (4 rows + 1)
#define L2PS     66                 // padded u64 stride per LUT pair (528B)

// ---------------- Device scratch ----------------
__device__ float g_h1[NG4 * O1 * RG];     // 4 MB, layout [g4][o][r]

// ---------------- f32x2 helpers (sm_10x packed fp32) ----------------
__device__ __forceinline__ unsigned long long pk2(float lo, float hi) {
    unsigned long long r;
    asm("mov.b64 %0, {%1, %2};" : "=l"(r) : "f"(lo), "f"(hi));
    return r;
}
__device__ __forceinline__ void upk2(float& lo, float& hi, unsigned long long v) {
    asm("mov.b64 {%0, %1}, %2;" : "=f"(lo), "=f"(hi) : "l"(v));
}
__device__ __forceinline__ unsigned long long fma2(unsigned long long a,
                                                   unsigned long long b,
                                                   unsigned long long c) {
    unsigned long long d;
    asm("fma.rn.f32x2 %0, %1, %2, %3;" : "=l"(d) : "l"(a), "l"(b), "l"(c));
    return d;
}
// a + x*(b-a) on both lanes
__device__ __forceinline__ unsigned long long lerp2(unsigned long long a,
                                                    unsigned long long b,
                                                    unsigned long long x,
                                                    unsigned long long nx) {
    return fma2(x, b, fma2(nx, a, a));
}

// ============ Kernel 1: thermometer (in-CTA) + layer 1 gather ============
// grid 64*2 = 128 CTAs (single wave), 512 threads.
// Writes g_h1 in kB's RG=4 layout: [g4 = row>>2][o][row&3].
__global__ __launch_bounds__(512)
void k01_layer1(const float* __restrict__ x,     const float* __restrict__ thr,
                const float* __restrict__ luts1, const int* __restrict__ idx1)
{
    __shared__ unsigned s_bits[RGA * 97];     // 8 rows x 96 words, stride 97
    __shared__ int      s_idx[A_OUT * 6];     // 24 KB

    const int g     = blockIdx.x >> 1;        // 8-row group
    const int os    = blockIdx.x & 1;
    const int obase = os * A_OUT;
    const int tid   = threadIdx.x;
    const int lane  = tid & 31;

    // ---- thermometer: 8 rows x 1024 features via warp ballots ----
    for (int i = tid; i < RGA * FEAT; i += 512) {
        const int r = i >> 10;
        const int f = i & 1023;
        float xv = __ldg(x + (g * RGA + r) * FEAT + f);
        unsigned b0 = __ballot_sync(0xFFFFFFFFu, xv > __ldg(thr + f * 3 + 0));
        unsigned b1 = __ballot_sync(0xFFFFFFFFu, xv > __ldg(thr + f * 3 + 1));
        unsigned b2 = __ballot_sync(0xFFFFFFFFu, xv > __ldg(thr + f * 3 + 2));
        if (lane == 0) {
            unsigned* wp = s_bits + r * 97 + (f >> 5);
            wp[0]  = b0;
            wp[32] = b1;
            wp[64] = b2;
        }
    }
    for (int i = tid; i < A_OUT * 6; i += 512)
        s_idx[i] = __ldg(idx1 + obase * 6 + i);
    __syncthreads();

    // ---- layer 1: pure gather, task t -> (o = t>>3, r = t&7) ----
    for (int t = tid; t < A_OUT * RGA; t += 512) {
        const int ol = t >> 3;
        const int r  = t & 7;
        const unsigned* bp = s_bits + r * 97;
        int code = 0;
        #pragma unroll
        for (int k = 0; k < 6; k++) {
            unsigned i  = (unsigned)s_idx[ol * 6 + k];
            unsigned f  = i / 3u;
            unsigned tt = i - f * 3u;
            unsigned wv = bp[tt * 32 + (f >> 5)];
            code = (code << 1) | (int)((wv >> (f & 31)) & 1u);
        }
        const int g4 = g * 2 + (r >> 2);
        g_h1[(g4 * O1 + obase + ol) * RG + (r & 3)] =
            __ldg(luts1 + (obase + ol) * NLUT + code);
    }
}

// ============ Kernel 2: layer 2 interp + class sums ============
// grid 128*5 = 640 CTAs, 512 threads, ~101 KB smem -> 2 CTAs/SM.
// One row per compute thread; x values loaded lazily per level (reg cap 64).
__global__ __launch_bounds__(512, 2)
void kB_layer2(const float* __restrict__ luts2, const int* __restrict__ idx2,
               float* __restrict__ out)
{
    extern __shared__ char smem[];
    float*              s_h1  = (float*)smem;                          // 2000*5 f (40 KB)
    unsigned long long* s_l2p = (unsigned long long*)(s_h1 + O1 * H1S);// 100*66 u64 (52.8 KB)
    int*                s_idx = (int*)(s_l2p + NPAIR * L2PS);          // 1200 i (4.8 KB)
    float*              s_h2  = (float*)(s_idx + B_OUT * 6);           // 800 f (3.2 KB)

    const int g     = blockIdx.x / B_OSPL;     // RG=4 row group, 0..127
    const int os    = blockIdx.x % B_OSPL;
    const int obase = os * B_OUT;
    const int tid   = threadIdx.x;

    // ---- stage h1: [o][r] contiguous -> smem stride-5 (scalar stores) ----
    {
        const float4* src = (const float4*)(g_h1 + g * O1 * RG);
        for (int i = tid; i < O1; i += 512) {
            float4 v = __ldg(src + i);
            float* d = s_h1 + i * H1S;
            d[0] = v.x; d[1] = v.y; d[2] = v.z; d[3] = v.w;
        }
    }
    // ---- stage luts2 pair-interleaved: s_l2p[p*66 + j] = (rowA[j], rowB[j]) ----
    for (int i = tid; i < NPAIR * (NLUT / 4); i += 512) {
        const int p = i >> 4, q = i & 15;
        float4 a = __ldg((const float4*)(luts2 + (obase + p) * NLUT) + q);
        float4 b = __ldg((const float4*)(luts2 + (obase + NPAIR + p) * NLUT) + q);
        unsigned long long* d = s_l2p + p * L2PS + q * 4;
        d[0] = pk2(a.x, b.x);
        d[1] = pk2(a.y, b.y);
        d[2] = pk2(a.z, b.z);
        d[3] = pk2(a.w, b.w);
    }
    for (int i = tid; i < B_OUT * 6; i += 512)
        s_idx[i] = __ldg(idx2 + obase * 6 + i);
    __syncthreads();

    if (tid < RG * NPAIR) {
        const int p = tid >> 2;       // pair id (4 lanes share -> LDS broadcast)
        const int r = tid & 3;        // row within group
        const unsigned long long* Lp  = s_l2p + p * L2PS;
        const int*                ipA = s_idx + p * 6;
        const int*                ipB = s_idx + (p + NPAIR) * 6;

        // levels x5, x4 straight from smem: 64 -> 16 (conflict-free LDS.128)
        unsigned long long xp5, xn5, xp4, xn4;
        {
            float a5 = s_h1[ipA[5] * H1S + r], b5 = s_h1[ipB[5] * H1S + r];
            float a4 = s_h1[ipA[4] * H1S + r], b4 = s_h1[ipB[4] * H1S + r];
            xp5 = pk2(a5, b5); xn5 = pk2(-a5, -b5);
            xp4 = pk2(a4, b4); xn4 = pk2(-a4, -b4);
        }
        unsigned long long u[16];
        #pragma unroll
        for (int t = 0; t < 16; t++) {
            ulonglong2 c01 = *(const ulonglong2*)(Lp + 4 * t);
            ulonglong2 c23 = *(const ulonglong2*)(Lp + 4 * t + 2);
            u[t] = lerp2(lerp2(c01.x, c01.y, xp5, xn5),
                         lerp2(c23.x, c23.y, xp5, xn5), xp4, xn4);
        }
        // levels x3..x0: load x lazily per level (keeps live regs low)
        #pragma unroll
        for (int k = 3; k >= 0; k--) {
            float xa = s_h1[ipA[k] * H1S + r], xb = s_h1[ipB[k] * H1S + r];
            unsigned long long xpk = pk2(xa, xb), xnk = pk2(-xa, -xb);
            const int m = 1 << k;
            #pragma unroll
            for (int j = 0; j < 8; j++) {
                if (j < m) u[j] = lerp2(u[2 * j], u[2 * j + 1], xpk, xnk);
            }
        }
        float hA, hB;
        upk2(hA, hB, u[0]);
        s_h2[p * RG + r]           = hA;    // local output p
        s_h2[(p + NPAIR) * RG + r] = hB;    // local output p+100
    }
    __syncthreads();

    // ---- deterministic fixed-order class sums: 2 classes x 4 rows ----
    if (tid < 2 * RG) {
        const int c = tid >> 2;
        const int r = tid & 3;
        const float* hp = s_h2 + c * NPAIR * RG + r;
        float s0 = 0.f, s1 = 0.f;
        #pragma unroll 4
        for (int j = 0; j < NPAIR; j += 2) {
            s0 += hp[(j + 0) * RG];
            s1 += hp[(j + 1) * RG];
        }
        out[(g * RG + r) * NCLS + os * 2 + c] = (s0 + s1) / TAU;
    }
}

// ================== launch ==================
extern "C" void kernel_launch(void* const* d_in, const int* in_sizes, int n_in,
                              void* d_out, int out_size)
{
    const float* x      = (const float*)d_in[0];
    const float* thr    = (const float*)d_in[1];
    const float* luts1  = (const float*)d_in[2];
    const int*   idx1   = (const int*)  d_in[3];
    const float* luts2  = (const float*)d_in[4];
    const int*   idx2   = (const int*)  d_in[5];
    float*       out    = (float*)d_out;

    const int smemB = O1 * H1S * 4 + NPAIR * L2PS * 8 + B_OUT * 6 * 4 + B_OUT * RG * 4;
    static bool attr_set = false;
    if (!attr_set) {
        cudaFuncSetAttribute(kB_layer2, cudaFuncAttributeMaxDynamicSharedMemorySize, smemB);
        attr_set = true;
    }

    k01_layer1<<<NGA * A_OSPL, 512>>>(x, thr, luts1, idx1);
    kB_layer2<<<NG4 * B_OSPL, 512, smemB>>>(luts2, idx2, out);
}

// round 6
// speedup vs baseline: 1.7610x; 1.1605x over previous
#include <cuda_runtime.h>

// ---------------- Problem constants ----------------
#define BATCH    512
#define FEAT     1024
#define O1       2000
#define O2       1000
#define NLUT     64
#define NCLS     10
#define TAU      3.3333333f

// kA: 8 rows per CTA
#define RGA      8
#define NGA      (BATCH / RGA)      // 64
#define A_OSPL   4
#define A_OUT    (O1 / A_OSPL)      // 500

// kB: 4 rows per CTA, 3 CTAs/SM
#define RG       4
#define NG4      (BATCH / RG)       // 128
#define B_OSPL   5
#define B_OUT    (O2 / B_OSPL)      // 200 = 2 classes
#define NPAIR    (B_OUT / 2)        // 100
#define L2PS     66                 // padded u64 stride per LUT pair
#define BTHREADS 448

// ---------------- Device scratch ----------------
__device__ float g_h1[NG4 * O1 * RG];     // 4 MB, layout [g4][o][r]

// ---------------- f32x2 helpers ----------------
__device__ __forceinline__ unsigned long long pk2(float lo, float hi) {
    unsigned long long r;
    asm("mov.b64 %0, {%1, %2};" : "=l"(r) : "f"(lo), "f"(hi));
    return r;
}
__device__ __forceinline__ void upk2(float& lo, float& hi, unsigned long long v) {
    asm("mov.b64 {%0, %1}, %2;" : "=f"(lo), "=f"(hi) : "l"(v));
}
__device__ __forceinline__ unsigned long long fma2(unsigned long long a,
                                                   unsigned long long b,
                                                   unsigned long long c) {
    unsigned long long d;
    asm("fma.rn.f32x2 %0, %1, %2, %3;" : "=l"(d) : "l"(a), "l"(b), "l"(c));
    return d;
}
__device__ __forceinline__ unsigned long long lerp2(unsigned long long a,
                                                    unsigned long long b,
                                                    unsigned long long x,
                                                    unsigned long long nx) {
    return fma2(x, b, fma2(nx, a, a));
}

// ============ Kernel 1: thermometer (in-CTA) + layer 1 gather ============
// grid 64*4 = 256 CTAs, 512 threads. Writes g_h1 in kB's RG=4 layout.
__global__ __launch_bounds__(512)
void k01_layer1(const float* __restrict__ x,     const float* __restrict__ thr,
                const float* __restrict__ luts1, const int* __restrict__ idx1)
{
    __shared__ unsigned s_bits[RGA * 97];
    __shared__ int      s_idx[A_OUT * 6];

    const int g     = blockIdx.x >> 2;
    const int os    = blockIdx.x & 3;
    const int obase = os * A_OUT;
    const int tid   = threadIdx.x;
    const int lane  = tid & 31;

    for (int i = tid; i < RGA * FEAT; i += 512) {
        const int r = i >> 10;
        const int f = i & 1023;
        float xv = __ldg(x + (g * RGA + r) * FEAT + f);
        unsigned b0 = __ballot_sync(0xFFFFFFFFu, xv > __ldg(thr + f * 3 + 0));
        unsigned b1 = __ballot_sync(0xFFFFFFFFu, xv > __ldg(thr + f * 3 + 1));
        unsigned b2 = __ballot_sync(0xFFFFFFFFu, xv > __ldg(thr + f * 3 + 2));
        if (lane == 0) {
            unsigned* wp = s_bits + r * 97 + (f >> 5);
            wp[0]  = b0;
            wp[32] = b1;
            wp[64] = b2;
        }
    }
    for (int i = tid; i < A_OUT * 6; i += 512)
        s_idx[i] = __ldg(idx1 + obase * 6 + i);
    __syncthreads();

    for (int t = tid; t < A_OUT * RGA; t += 512) {
        const int ol = t >> 3;
        const int r  = t & 7;
        const unsigned* bp = s_bits + r * 97;
        int code = 0;
        #pragma unroll
        for (int k = 0; k < 6; k++) {
            unsigned i  = (unsigned)s_idx[ol * 6 + k];
            unsigned f  = i / 3u;
            unsigned tt = i - f * 3u;
            unsigned wv = bp[tt * 32 + (f >> 5)];
            code = (code << 1) | (int)((wv >> (f & 31)) & 1u);
        }
        const int g4 = g * 2 + (r >> 2);
        g_h1[(g4 * O1 + obase + ol) * RG + (r & 3)] =
            __ldg(luts1 + (obase + ol) * NLUT + code);
    }
}

// ============ Kernel 2: layer 2 interp + class sums ============
// grid 128*5 = 640 CTAs, 448 threads, ~61 KB smem -> 3 CTAs/SM (48-reg budget).
// LUT staged per-pair as (a, b-a) at level-5 granularity: first contraction
// is a single FMA2. h1 read directly from L2 (g_h1), prefetched up front.
__global__ __launch_bounds__(BTHREADS, 3)
void kB_layer2(const float* __restrict__ luts2, const int* __restrict__ idx2,
               float* __restrict__ out)
{
    extern __shared__ char smem[];
    unsigned long long* s_l2p = (unsigned long long*)smem;        // 100*66 u64 (52.8 KB)
    int*                s_idx = (int*)(s_l2p + NPAIR * L2PS);     // 1200 i (4.8 KB)
    float*              s_h2  = (float*)(s_idx + B_OUT * 6);      // 800 f (3.2 KB)

    const int g     = blockIdx.x / B_OSPL;
    const int os    = blockIdx.x % B_OSPL;
    const int obase = os * B_OUT;
    const int tid   = threadIdx.x;

    // ---- stage luts2: pair-interleaved, level-5 pairs stored as (a, b-a) ----
    for (int i = tid; i < NPAIR * (NLUT / 4); i += BTHREADS) {
        const int p = i >> 4, q = i & 15;
        float4 a = __ldg((const float4*)(luts2 + (obase + p) * NLUT) + q);
        float4 b = __ldg((const float4*)(luts2 + (obase + NPAIR + p) * NLUT) + q);
        unsigned long long* d = s_l2p + p * L2PS + q * 4;
        d[0] = pk2(a.x, b.x);
        d[1] = pk2(a.y - a.x, b.y - b.x);
        d[2] = pk2(a.z, b.z);
        d[3] = pk2(a.w - a.z, b.w - b.z);
    }
    for (int i = tid; i < B_OUT * 6; i += BTHREADS)
        s_idx[i] = __ldg(idx2 + obase * 6 + i);
    __syncthreads();

    if (tid < RG * NPAIR) {
        const int p = tid >> 2;     // pair id (4 lanes share -> LDS broadcast)
        const int r = tid & 3;      // row within group
        const unsigned long long* Lp = s_l2p + p * L2PS;

        // ---- prefetch all x packs from g_h1 (L2), full MLP ----
        const float* h1g = g_h1 + (size_t)g * O1 * RG + r;
        unsigned long long xp[6], xn[5];
        #pragma unroll
        for (int k = 0; k < 6; k++) {
            float xa = __ldg(h1g + s_idx[p * 6 + k] * RG);
            float xb = __ldg(h1g + s_idx[(p + NPAIR) * 6 + k] * RG);
            xp[k] = pk2(xa, xb);
            if (k < 5) xn[k] = pk2(-xa, -xb);
        }

        // ---- levels x5..x2 per 16-block -> u[4] ----
        unsigned long long u[4];
        #pragma unroll
        for (int t = 0; t < 4; t++) {
            const unsigned long long* Lt = Lp + 16 * t;
            ulonglong2 c;
            unsigned long long w0, w1, v0, v1, h0, h1v;
            c = *(const ulonglong2*)(Lt + 0);  w0 = fma2(xp[5], c.y, c.x);
            c = *(const ulonglong2*)(Lt + 2);  w1 = fma2(xp[5], c.y, c.x);
            v0 = lerp2(w0, w1, xp[4], xn[4]);
            c = *(const ulonglong2*)(Lt + 4);  w0 = fma2(xp[5], c.y, c.x);
            c = *(const ulonglong2*)(Lt + 6);  w1 = fma2(xp[5], c.y, c.x);
            v1 = lerp2(w0, w1, xp[4], xn[4]);
            h0 = lerp2(v0, v1, xp[3], xn[3]);
            c = *(const ulonglong2*)(Lt + 8);  w0 = fma2(xp[5], c.y, c.x);
            c = *(const ulonglong2*)(Lt + 10); w1 = fma2(xp[5], c.y, c.x);
            v0 = lerp2(w0, w1, xp[4], xn[4]);
            c = *(const ulonglong2*)(Lt + 12); w0 = fma2(xp[5], c.y, c.x);
            c = *(const ulonglong2*)(Lt + 14); w1 = fma2(xp[5], c.y, c.x);
            v1 = lerp2(w0, w1, xp[4], xn[4]);
            h1v = lerp2(v0, v1, xp[3], xn[3]);
            u[t] = lerp2(h0, h1v, xp[2], xn[2]);
        }
        // ---- tail: x1 then x0 ----
        unsigned long long t0 = lerp2(u[0], u[1], xp[1], xn[1]);
        unsigned long long t1 = lerp2(u[2], u[3], xp[1], xn[1]);
        unsigned long long res = lerp2(t0, t1, xp[0], xn[0]);

        float hA, hB;
        upk2(hA, hB, res);
        s_h2[p * RG + r]           = hA;
        s_h2[(p + NPAIR) * RG + r] = hB;
    }
    __syncthreads();

    // ---- deterministic fixed-order class sums: 2 classes x 4 rows ----
    if (tid < 2 * RG) {
        const int c = tid >> 2;
        const int r = tid & 3;
        const float* hp = s_h2 + c * NPAIR * RG + r;
        float s0 = 0.f, s1 = 0.f;
        #pragma unroll 4
        for (int j = 0; j < NPAIR; j += 2) {
            s0 += hp[(j + 0) * RG];
            s1 += hp[(j + 1) * RG];
        }
        out[(g * RG + r) * NCLS + os * 2 + c] = (s0 + s1) / TAU;
    }
}

// ================== launch ==================
extern "C" void kernel_launch(void* const* d_in, const int* in_sizes, int n_in,
                              void* d_out, int out_size)
{
    const float* x      = (const float*)d_in[0];
    const float* thr    = (const float*)d_in[1];
    const float* luts1  = (const float*)d_in[2];
    const int*   idx1   = (const int*)  d_in[3];
    const float* luts2  = (const float*)d_in[4];
    const int*   idx2   = (const int*)  d_in[5];
    float*       out    = (float*)d_out;

    const int smemB = NPAIR * L2PS * 8 + B_OUT * 6 * 4 + B_OUT * RG * 4;
    static bool attr_set = false;
    if (!attr_set) {
        cudaFuncSetAttribute(kB_layer2, cudaFuncAttributeMaxDynamicSharedMemorySize, smemB);
        attr_set = true;
    }

    k01_layer1<<<NGA * A_OSPL, 512>>>(x, thr, luts1, idx1);
    kB_layer2<<<NG4 * B_OSPL, BTHREADS, smemB>>>(luts2, idx2, out);
}

// round 7
// speedup vs baseline: 1.9879x; 1.1289x over previous
#include <cuda_runtime.h>

// ---------------- Problem constants ----------------
#define BATCH    512
#define FEAT     1024
#define O1       2000
#define O2       1000
#define NLUT     64
#define NCLS     10
#define TAU      3.3333333f

// Row grouping: 8 rows per CTA everywhere
#define RG       8
#define NG       (BATCH / RG)       // 64

// kA output split
#define A_OSPL   4
#define A_OUT    (O1 / A_OSPL)      // 500

// kB output split: 10 slices -> 100 outputs = exactly 1 class per CTA
#define B_OSPL   10
#define B_OUT    (O2 / B_OSPL)      // 100
#define NPAIR    (B_OUT / 2)        // 50
#define L2PS     66                 // padded u64 stride per LUT pair (528B)
#define BTHREADS 448

// ---------------- Device scratch ----------------
__device__ float g_h1[NG * O1 * RG];      // 4 MB, layout [g][o][r], r in 0..7

// ---------------- f32x2 helpers ----------------
__device__ __forceinline__ unsigned long long pk2(float lo, float hi) {
    unsigned long long r;
    asm("mov.b64 %0, {%1, %2};" : "=l"(r) : "f"(lo), "f"(hi));
    return r;
}
__device__ __forceinline__ void upk2(float& lo, float& hi, unsigned long long v) {
    asm("mov.b64 {%0, %1}, %2;" : "=f"(lo), "=f"(hi) : "l"(v));
}
__device__ __forceinline__ unsigned long long fma2(unsigned long long a,
                                                   unsigned long long b,
                                                   unsigned long long c) {
    unsigned long long d;
    asm("fma.rn.f32x2 %0, %1, %2, %3;" : "=l"(d) : "l"(a), "l"(b), "l"(c));
    return d;
}
__device__ __forceinline__ unsigned long long lerp2(unsigned long long a,
                                                    unsigned long long b,
                                                    unsigned long long x,
                                                    unsigned long long nx) {
    return fma2(x, b, fma2(nx, a, a));
}

// ============ Kernel 1: thermometer (in-CTA) + layer 1 gather ============
// grid 64*4 = 256 CTAs, 512 threads.
__global__ __launch_bounds__(512)
void k01_layer1(const float* __restrict__ x,     const float* __restrict__ thr,
                const float* __restrict__ luts1, const int* __restrict__ idx1)
{
    __shared__ unsigned s_bits[RG * 97];
    __shared__ int      s_idx[A_OUT * 6];

    const int g     = blockIdx.x >> 2;
    const int os    = blockIdx.x & 3;
    const int obase = os * A_OUT;
    const int tid   = threadIdx.x;
    const int lane  = tid & 31;

    for (int i = tid; i < RG * FEAT; i += 512) {
        const int r = i >> 10;
        const int f = i & 1023;
        float xv = __ldg(x + (g * RG + r) * FEAT + f);
        unsigned b0 = __ballot_sync(0xFFFFFFFFu, xv > __ldg(thr + f * 3 + 0));
        unsigned b1 = __ballot_sync(0xFFFFFFFFu, xv > __ldg(thr + f * 3 + 1));
        unsigned b2 = __ballot_sync(0xFFFFFFFFu, xv > __ldg(thr + f * 3 + 2));
        if (lane == 0) {
            unsigned* wp = s_bits + r * 97 + (f >> 5);
            wp[0]  = b0;
            wp[32] = b1;
            wp[64] = b2;
        }
    }
    for (int i = tid; i < A_OUT * 6; i += 512)
        s_idx[i] = __ldg(idx1 + obase * 6 + i);
    __syncthreads();

    // layer 1: pure gather, task t -> (o = t>>3, r = t&7); unroll 2 for MLP
    #pragma unroll 2
    for (int t = tid; t < A_OUT * RG; t += 512) {
        const int ol = t >> 3;
        const int r  = t & 7;
        const unsigned* bp = s_bits + r * 97;
        int code = 0;
        #pragma unroll
        for (int k = 0; k < 6; k++) {
            unsigned i  = (unsigned)s_idx[ol * 6 + k];
            unsigned f  = i / 3u;
            unsigned tt = i - f * 3u;
            unsigned wv = bp[tt * 32 + (f >> 5)];
            code = (code << 1) | (int)((wv >> (f & 31)) & 1u);
        }
        g_h1[(g * O1 + obase + ol) * RG + r] =
            __ldg(luts1 + (obase + ol) * NLUT + code);
    }
}

// ============ Kernel 2: layer 2 interp + one class sum per CTA ============
// grid 64*10 = 640 CTAs, 448 threads, ~32 KB smem -> 4 CTAs/SM (36-reg cap).
// Pair (p, p+50) packed in f32x2 lanes; level-5 entries staged as (a, b-a).
// h1 read from L2; 8 lanes share pair -> one 32B sector per x-load.
__global__ __launch_bounds__(BTHREADS, 4)
void kB_layer2(const float* __restrict__ luts2, const int* __restrict__ idx2,
               float* __restrict__ out)
{
    extern __shared__ char smem[];
    unsigned long long* s_l2p = (unsigned long long*)smem;        // 50*66 u64 (26.4 KB)
    int*                s_idx = (int*)(s_l2p + NPAIR * L2PS);     // 600 i (2.4 KB)
    float*              s_h2  = (float*)(s_idx + B_OUT * 6);      // 800 f (3.2 KB)

    const int g     = blockIdx.x / B_OSPL;     // 8-row group, 0..63
    const int os    = blockIdx.x % B_OSPL;     // class id
    const int obase = os * B_OUT;
    const int tid   = threadIdx.x;

    // ---- stage luts2 slice: pair-interleaved, level-5 pairs as (a, b-a) ----
    for (int i = tid; i < NPAIR * (NLUT / 4); i += BTHREADS) {
        const int p = i >> 4, q = i & 15;
        float4 a = __ldg((const float4*)(luts2 + (obase + p) * NLUT) + q);
        float4 b = __ldg((const float4*)(luts2 + (obase + NPAIR + p) * NLUT) + q);
        unsigned long long* d = s_l2p + p * L2PS + q * 4;
        d[0] = pk2(a.x, b.x);
        d[1] = pk2(a.y - a.x, b.y - b.x);
        d[2] = pk2(a.z, b.z);
        d[3] = pk2(a.w - a.z, b.w - b.z);
    }
    for (int i = tid; i < B_OUT * 6; i += BTHREADS)
        s_idx[i] = __ldg(idx2 + obase * 6 + i);
    __syncthreads();

    if (tid < RG * NPAIR) {                  // 400 compute threads
        const int p = tid >> 3;              // pair id (8 lanes share)
        const int r = tid & 7;               // row within group
        const unsigned long long* Lp = s_l2p + p * L2PS;
        const float* h1g = g_h1 + (size_t)g * O1 * RG + r;
        const int* ipA = s_idx + p * 6;
        const int* ipB = s_idx + (p + NPAIR) * 6;

        // prefetch x5..x2 (x1, x0 loaded lazily to cap live registers)
        unsigned long long xp5, xp4, xn4, xp3, xn3, xp2, xn2;
        {
            float a, b;
            a = __ldg(h1g + ipA[5] * RG); b = __ldg(h1g + ipB[5] * RG);
            xp5 = pk2(a, b);
            a = __ldg(h1g + ipA[4] * RG); b = __ldg(h1g + ipB[4] * RG);
            xp4 = pk2(a, b); xn4 = pk2(-a, -b);
            a = __ldg(h1g + ipA[3] * RG); b = __ldg(h1g + ipB[3] * RG);
            xp3 = pk2(a, b); xn3 = pk2(-a, -b);
            a = __ldg(h1g + ipA[2] * RG); b = __ldg(h1g + ipB[2] * RG);
            xp2 = pk2(a, b); xn2 = pk2(-a, -b);
        }

        // levels x5..x2 per 16-block -> u[4]
        unsigned long long u[4];
        #pragma unroll
        for (int t = 0; t < 4; t++) {
            const unsigned long long* Lt = Lp + 16 * t;
            ulonglong2 c;
            unsigned long long w0, w1, v0, v1, h0, h1v;
            c = *(const ulonglong2*)(Lt + 0);  w0 = fma2(xp5, c.y, c.x);
            c = *(const ulonglong2*)(Lt + 2);  w1 = fma2(xp5, c.y, c.x);
            v0 = lerp2(w0, w1, xp4, xn4);
            c = *(const ulonglong2*)(Lt + 4);  w0 = fma2(xp5, c.y, c.x);
            c = *(const ulonglong2*)(Lt + 6);  w1 = fma2(xp5, c.y, c.x);
            v1 = lerp2(w0, w1, xp4, xn4);
            h0 = lerp2(v0, v1, xp3, xn3);
            c = *(const ulonglong2*)(Lt + 8);  w0 = fma2(xp5, c.y, c.x);
            c = *(const ulonglong2*)(Lt + 10); w1 = fma2(xp5, c.y, c.x);
            v0 = lerp2(w0, w1, xp4, xn4);
            c = *(const ulonglong2*)(Lt + 12); w0 = fma2(xp5, c.y, c.x);
            c = *(const ulonglong2*)(Lt + 14); w1 = fma2(xp5, c.y, c.x);
            v1 = lerp2(w0, w1, xp4, xn4);
            h1v = lerp2(v0, v1, xp3, xn3);
            u[t] = lerp2(h0, h1v, xp2, xn2);
        }
        // tail: x1 then x0 (lazy loads)
        float a1, b1;
        a1 = __ldg(h1g + ipA[1] * RG); b1 = __ldg(h1g + ipB[1] * RG);
        unsigned long long xp1 = pk2(a1, b1), xn1 = pk2(-a1, -b1);
        unsigned long long t0 = lerp2(u[0], u[1], xp1, xn1);
        unsigned long long t1 = lerp2(u[2], u[3], xp1, xn1);
        a1 = __ldg(h1g + ipA[0] * RG); b1 = __ldg(h1g + ipB[0] * RG);
        unsigned long long xp0 = pk2(a1, b1), xn0 = pk2(-a1, -b1);
        unsigned long long res = lerp2(t0, t1, xp0, xn0);

        float hA, hB;
        upk2(hA, hB, res);
        s_h2[p * RG + r]           = hA;    // local output p
        s_h2[(p + NPAIR) * RG + r] = hB;    // local output p+50
    }
    __syncthreads();

    // ---- deterministic fixed-order class sum: 1 class x 8 rows ----
    if (tid < RG) {
        const int r = tid;
        const float* hp = s_h2 + r;
        float s0 = 0.f, s1 = 0.f;
        #pragma unroll 4
        for (int j = 0; j < B_OUT; j += 2) {
            s0 += hp[(j + 0) * RG];
            s1 += hp[(j + 1) * RG];
        }
        out[(g * RG + r) * NCLS + os] = (s0 + s1) / TAU;
    }
}

// ================== launch ==================
extern "C" void kernel_launch(void* const* d_in, const int* in_sizes, int n_in,
                              void* d_out, int out_size)
{
    const float* x      = (const float*)d_in[0];
    const float* thr    = (const float*)d_in[1];
    const float* luts1  = (const float*)d_in[2];
    const int*   idx1   = (const int*)  d_in[3];
    const float* luts2  = (const float*)d_in[4];
    const int*   idx2   = (const int*)  d_in[5];
    float*       out    = (float*)d_out;

    const int smemB = NPAIR * L2PS * 8 + B_OUT * 6 * 4 + B_OUT * RG * 4;
    static bool attr_set = false;
    if (!attr_set) {
        cudaFuncSetAttribute(kB_layer2, cudaFuncAttributeMaxDynamicSharedMemorySize, smemB);
        attr_set = true;
    }

    k01_layer1<<<NG * A_OSPL, 512>>>(x, thr, luts1, idx1);
    kB_layer2<<<NG * B_OSPL, BTHREADS, smemB>>>(luts2, idx2, out);
}

// round 8
// speedup vs baseline: 2.0627x; 1.0376x over previous
#include <cuda_runtime.h>

// ---------------- Problem constants ----------------
#define BATCH    512
#define FEAT     1024
#define O1       2000
#define O2       1000
#define NLUT     64
#define NCLS     10
#define TAU      3.3333333f

#define RG       8
#define NG       (BATCH / RG)       // 64

#define A_OSPL   4
#define A_OUT    (O1 / A_OSPL)      // 500

#define B_OSPL   10
#define B_OUT    (O2 / B_OSPL)      // 100 = 1 class
#define NPAIR    (B_OUT / 2)        // 50
#define L2PS     66                 // padded u64 stride per LUT pair
#define BTHREADS 448

// ---------------- Device scratch ----------------
__device__ float g_h1[NG * O1 * RG];      // 4 MB, layout [g][o][r]

// ---------------- f32x2 helpers ----------------
__device__ __forceinline__ unsigned long long pk2(float lo, float hi) {
    unsigned long long r;
    asm("mov.b64 %0, {%1, %2};" : "=l"(r) : "f"(lo), "f"(hi));
    return r;
}
__device__ __forceinline__ void upk2(float& lo, float& hi, unsigned long long v) {
    asm("mov.b64 {%0, %1}, %2;" : "=f"(lo), "=f"(hi) : "l"(v));
}
__device__ __forceinline__ unsigned long long fma2(unsigned long long a,
                                                   unsigned long long b,
                                                   unsigned long long c) {
    unsigned long long d;
    asm("fma.rn.f32x2 %0, %1, %2, %3;" : "=l"(d) : "l"(a), "l"(b), "l"(c));
    return d;
}
__device__ __forceinline__ unsigned long long lerp2(unsigned long long a,
                                                    unsigned long long b,
                                                    unsigned long long x,
                                                    unsigned long long nx) {
    return fma2(x, b, fma2(nx, a, a));
}

// ============ Kernel 1: thermometer + layer 1 gather ============
// grid 64*4 = 256 CTAs, 512 threads. thr staged to smem (conflict-free LDS).
__global__ __launch_bounds__(512)
void k01_layer1(const float* __restrict__ x,     const float* __restrict__ thr,
                const float* __restrict__ luts1, const int* __restrict__ idx1)
{
    __shared__ float    s_thr[FEAT * 3];      // 12 KB
    __shared__ unsigned s_bits[RG * 97];      // 3.1 KB
    __shared__ int      s_idx[A_OUT * 6];     // 12 KB

    const int g     = blockIdx.x >> 2;
    const int os    = blockIdx.x & 3;
    const int obase = os * A_OUT;
    const int tid   = threadIdx.x;
    const int lane  = tid & 31;

    // stage thr (coalesced float4) + idx slice
    for (int i = tid; i < FEAT * 3 / 4; i += 512)
        ((float4*)s_thr)[i] = __ldg((const float4*)thr + i);
    for (int i = tid; i < A_OUT * 6; i += 512)
        s_idx[i] = __ldg(idx1 + obase * 6 + i);
    __syncthreads();

    // thermometer: thr from smem (bank-conflict-free stride-3)
    for (int i = tid; i < RG * FEAT; i += 512) {
        const int r = i >> 10;
        const int f = i & 1023;
        float xv = __ldg(x + (g * RG + r) * FEAT + f);
        float t0 = s_thr[f * 3 + 0];
        float t1 = s_thr[f * 3 + 1];
        float t2 = s_thr[f * 3 + 2];
        unsigned b0 = __ballot_sync(0xFFFFFFFFu, xv > t0);
        unsigned b1 = __ballot_sync(0xFFFFFFFFu, xv > t1);
        unsigned b2 = __ballot_sync(0xFFFFFFFFu, xv > t2);
        if (lane == 0) {
            unsigned* wp = s_bits + r * 97 + (f >> 5);
            wp[0]  = b0;
            wp[32] = b1;
            wp[64] = b2;
        }
    }
    __syncthreads();

    // layer 1: pure gather, task t -> (o = t>>3, r = t&7)
    #pragma unroll 2
    for (int t = tid; t < A_OUT * RG; t += 512) {
        const int ol = t >> 3;
        const int r  = t & 7;
        const unsigned* bp = s_bits + r * 97;
        int code = 0;
        #pragma unroll
        for (int k = 0; k < 6; k++) {
            unsigned i  = (unsigned)s_idx[ol * 6 + k];
            unsigned f  = i / 3u;
            unsigned tt = i - f * 3u;
            unsigned wv = bp[tt * 32 + (f >> 5)];
            code = (code << 1) | (int)((wv >> (f & 31)) & 1u);
        }
        g_h1[(g * O1 + obase + ol) * RG + r] =
            __ldg(luts1 + (obase + ol) * NLUT + code);
    }
}

// ============ Kernel 2: layer 2 interp + one class sum per CTA ============
// grid 640 CTAs, 448 threads, ~30 KB smem, 4 CTAs/SM.
// x/idx prefetch issued BEFORE the staging loop: its L2 latency is covered
// by the staging work; post-barrier path is pure LDS + FMA2.
__global__ __launch_bounds__(BTHREADS, 4)
void kB_layer2(const float* __restrict__ luts2, const int* __restrict__ idx2,
               float* __restrict__ out)
{
    extern __shared__ char smem[];
    unsigned long long* s_l2p = (unsigned long long*)smem;     // 50*66 u64 (26.4 KB)
    float*              s_h2  = (float*)(s_l2p + NPAIR * L2PS);// 800 f (3.2 KB)

    const int g     = blockIdx.x / B_OSPL;
    const int os    = blockIdx.x % B_OSPL;
    const int obase = os * B_OUT;
    const int tid   = threadIdx.x;

    // ---- prefetch idx + x for compute threads (overlaps with staging) ----
    float xa[6], xb[6];
    int p = 0, r = 0;
    const bool is_comp = (tid < RG * NPAIR);
    if (is_comp) {
        p = tid >> 3;                 // pair id (8 lanes share)
        r = tid & 7;                  // row within group
        const int* iA = idx2 + (obase + p) * 6;
        const int* iB = idx2 + (obase + NPAIR + p) * 6;
        const float* h1g = g_h1 + (size_t)g * O1 * RG + r;
        #pragma unroll
        for (int k = 0; k < 6; k++) {
            xa[k] = __ldg(h1g + __ldg(iA + k) * RG);
            xb[k] = __ldg(h1g + __ldg(iB + k) * RG);
        }
    }

    // ---- stage luts2 slice: pair-interleaved, level-5 pairs as (a, b-a) ----
    for (int i = tid; i < NPAIR * (NLUT / 4); i += BTHREADS) {
        const int pp = i >> 4, q = i & 15;
        float4 a = __ldg((const float4*)(luts2 + (obase + pp) * NLUT) + q);
        float4 b = __ldg((const float4*)(luts2 + (obase + NPAIR + pp) * NLUT) + q);
        unsigned long long* d = s_l2p + pp * L2PS + q * 4;
        d[0] = pk2(a.x, b.x);
        d[1] = pk2(a.y - a.x, b.y - b.x);
        d[2] = pk2(a.z, b.z);
        d[3] = pk2(a.w - a.z, b.w - b.z);
    }
    __syncthreads();

    if (is_comp) {
        const unsigned long long* Lp = s_l2p + p * L2PS;

        unsigned long long xp5 = pk2(xa[5], xb[5]);
        unsigned long long xp4 = pk2(xa[4], xb[4]), xn4 = pk2(-xa[4], -xb[4]);
        unsigned long long xp3 = pk2(xa[3], xb[3]), xn3 = pk2(-xa[3], -xb[3]);
        unsigned long long xp2 = pk2(xa[2], xb[2]), xn2 = pk2(-xa[2], -xb[2]);

        // levels x5..x2 per 16-block -> u[4]
        unsigned long long u[4];
        #pragma unroll
        for (int t = 0; t < 4; t++) {
            const unsigned long long* Lt = Lp + 16 * t;
            ulonglong2 c;
            unsigned long long w0, w1, v0, v1, h0, h1v;
            c = *(const ulonglong2*)(Lt + 0);  w0 = fma2(xp5, c.y, c.x);
            c = *(const ulonglong2*)(Lt + 2);  w1 = fma2(xp5, c.y, c.x);
            v0 = lerp2(w0, w1, xp4, xn4);
            c = *(const ulonglong2*)(Lt + 4);  w0 = fma2(xp5, c.y, c.x);
            c = *(const ulonglong2*)(Lt + 6);  w1 = fma2(xp5, c.y, c.x);
            v1 = lerp2(w0, w1, xp4, xn4);
            h0 = lerp2(v0, v1, xp3, xn3);
            c = *(const ulonglong2*)(Lt + 8);  w0 = fma2(xp5, c.y, c.x);
            c = *(const ulonglong2*)(Lt + 10); w1 = fma2(xp5, c.y, c.x);
            v0 = lerp2(w0, w1, xp4, xn4);
            c = *(const ulonglong2*)(Lt + 12); w0 = fma2(xp5, c.y, c.x);
            c = *(const ulonglong2*)(Lt + 14); w1 = fma2(xp5, c.y, c.x);
            v1 = lerp2(w0, w1, xp4, xn4);
            h1v = lerp2(v0, v1, xp3, xn3);
            u[t] = lerp2(h0, h1v, xp2, xn2);
        }
        // tail: x1 then x0
        unsigned long long xp1 = pk2(xa[1], xb[1]), xn1 = pk2(-xa[1], -xb[1]);
        unsigned long long t0 = lerp2(u[0], u[1], xp1, xn1);
        unsigned long long t1 = lerp2(u[2], u[3], xp1, xn1);
        unsigned long long xp0 = pk2(xa[0], xb[0]), xn0 = pk2(-xa[0], -xb[0]);
        unsigned long long res = lerp2(t0, t1, xp0, xn0);

        float hA, hB;
        upk2(hA, hB, res);
        s_h2[p * RG + r]           = hA;
        s_h2[(p + NPAIR) * RG + r] = hB;
    }
    __syncthreads();

    // ---- deterministic fixed-order class sum ----
    if (tid < RG) {
        const float* hp = s_h2 + tid;
        float s0 = 0.f, s1 = 0.f;
        #pragma unroll 4
        for (int j = 0; j < B_OUT; j += 2) {
            s0 += hp[(j + 0) * RG];
            s1 += hp[(j + 1) * RG];
        }
        out[(g * RG + tid) * NCLS + os] = (s0 + s1) / TAU;
    }
}

// ================== launch ==================
extern "C" void kernel_launch(void* const* d_in, const int* in_sizes, int n_in,
                              void* d_out, int out_size)
{
    const float* x      = (const float*)d_in[0];
    const float* thr    = (const float*)d_in[1];
    const float* luts1  = (const float*)d_in[2];
    const int*   idx1   = (const int*)  d_in[3];
    const float* luts2  = (const float*)d_in[4];
    const int*   idx2   = (const int*)  d_in[5];
    float*       out    = (float*)d_out;

    const int smemB = NPAIR * L2PS * 8 + B_OUT * RG * 4;
    static bool attr_set = false;
    if (!attr_set) {
        cudaFuncSetAttribute(kB_layer2, cudaFuncAttributeMaxDynamicSharedMemorySize, smemB);
        attr_set = true;
    }

    k01_layer1<<<NG * A_OSPL, 512>>>(x, thr, luts1, idx1);
    kB_layer2<<<NG * B_OSPL, BTHREADS, smemB>>>(luts2, idx2, out);
}